// round 2
// baseline (speedup 1.0000x reference)
#include <cuda_runtime.h>
#include <cstdint>

// ============================================================================
// Grouped GEMM (MoE ParallelExperts): out[T,N] = concat_e( A_e @ W_e^T )
//   A: [16384, 2048] fp32, W: [8, 8192, 2048] fp32, 2048 tokens/expert (static)
// tf32 mma.sync (m16n8k8) + cp.async 3-stage pipeline.
// NOTE: harness compiles PTX at target sm_103 (no 'a') -> tcgen05 unavailable;
// mma.sync is the fastest arch-agnostic tensor path.
// ============================================================================

#define M_TOTAL 16384
#define K_TOTAL 2048
#define N_TOTAL 8192
#define NUM_EXPERTS 8
#define M_PER_EXPERT 2048

#define BM 128
#define BN 256
#define BK 32
#define STAGES 3
#define K_ITERS (K_TOTAL / BK)            // 64
#define THREADS 256

#define LDA 36                             // padded word stride: bank-conflict-free frags
#define LDB 36
#define A_STAGE_WORDS (BM * LDA)           // 4608
#define B_STAGE_WORDS (BN * LDB)           // 9216
#define STAGE_WORDS (A_STAGE_WORDS + B_STAGE_WORDS)
#define SMEM_BYTES (STAGES * STAGE_WORDS * 4)   // 165888

#define M_TILES_PER_E (M_PER_EXPERT / BM)  // 16
#define N_TILES (N_TOTAL / BN)             // 32
#define TILES_PER_E (M_TILES_PER_E * N_TILES)
#define GRID_TILES (NUM_EXPERTS * TILES_PER_E)  // 4096

// warp grid 2(m) x 4(n); warp tile 64x64
#define WM 64
#define WN 64
#define MF 4   // m-frags of 16 rows
#define NF 8   // n-frags of 8 cols

// ---------------------------------------------------------------- helpers
__device__ __forceinline__ uint32_t smem_u32(const void* p) {
    uint32_t a;
    asm("{ .reg .u64 t; cvta.to.shared.u64 t, %1; cvt.u32.u64 %0, t; }" : "=r"(a) : "l"(p));
    return a;
}

__device__ __forceinline__ void cp_async16(uint32_t dst, const void* src) {
    asm volatile("cp.async.cg.shared.global [%0], [%1], 16;" :: "r"(dst), "l"(src));
}
#define CP_COMMIT() asm volatile("cp.async.commit_group;" ::: "memory")
#define CP_WAIT(n)  asm volatile("cp.async.wait_group %0;" :: "n"(n) : "memory")

__device__ __forceinline__ uint32_t f2tf32(float f) {
    uint32_t u;
    asm("cvt.rna.tf32.f32 %0, %1;" : "=r"(u) : "f"(f));
    return u;
}

__device__ __forceinline__ void mma_tf32(float* c, const uint32_t* a, uint32_t b0, uint32_t b1) {
    asm volatile(
        "mma.sync.aligned.m16n8k8.row.col.f32.tf32.tf32.f32 "
        "{%0,%1,%2,%3}, {%4,%5,%6,%7}, {%8,%9}, {%0,%1,%2,%3};"
        : "+f"(c[0]), "+f"(c[1]), "+f"(c[2]), "+f"(c[3])
        : "r"(a[0]), "r"(a[1]), "r"(a[2]), "r"(a[3]), "r"(b0), "r"(b1));
}

// ---------------------------------------------------------------- stage load
__device__ __forceinline__ void load_stage(uint32_t stage_addr, const float* Abase,
                                           const float* Wbase, int kiter, int tid) {
    const char* asrc = (const char*)Abase + (size_t)kiter * (BK * 4);
#pragma unroll
    for (int i = 0; i < 4; i++) {               // A: 128 rows x 8 chunks = 1024
        int q = tid + i * THREADS;
        int row = q >> 3;
        int c = (q & 7) * 16;
        cp_async16(stage_addr + (uint32_t)(row * (LDA * 4) + c),
                   asrc + (size_t)row * (K_TOTAL * 4) + c);
    }
    const char* bsrc = (const char*)Wbase + (size_t)kiter * (BK * 4);
    uint32_t bdst = stage_addr + A_STAGE_WORDS * 4;
#pragma unroll
    for (int i = 0; i < 8; i++) {               // B: 256 rows x 8 chunks = 2048
        int q = tid + i * THREADS;
        int row = q >> 3;
        int c = (q & 7) * 16;
        cp_async16(bdst + (uint32_t)(row * (LDB * 4) + c),
                   bsrc + (size_t)row * (K_TOTAL * 4) + c);
    }
}

// ---------------------------------------------------------------- kernel
__global__ void __launch_bounds__(THREADS, 1)
moe_tf32_mma(const float* __restrict__ A, const float* __restrict__ W,
             float* __restrict__ out) {
    extern __shared__ float smem[];
    uint32_t sb = smem_u32(smem);
    int tid = threadIdx.x;
    int lane = tid & 31;
    int warp = tid >> 5;
    int wm = warp >> 2;        // 0..1
    int wn = warp & 3;         // 0..3
    int g = lane >> 2;         // group id 0..7
    int tg = lane & 3;         // thread-in-group 0..3

    // tile mapping: expert-major, m fast within expert
    int b = blockIdx.x;
    int e = b / TILES_PER_E;
    int loc = b % TILES_PER_E;
    int m_idx = loc & (M_TILES_PER_E - 1);
    int n_idx = loc >> 4;
    int m0 = e * M_PER_EXPERT + m_idx * BM;
    int n0 = n_idx * BN;

    const float* Ab = A + (size_t)m0 * K_TOTAL;
    const float* Wb = W + ((size_t)e * N_TOTAL + (size_t)n0) * K_TOTAL;

    float acc[MF][NF][4];
#pragma unroll
    for (int mf = 0; mf < MF; mf++)
#pragma unroll
        for (int nf = 0; nf < NF; nf++)
#pragma unroll
            for (int r = 0; r < 4; r++) acc[mf][nf][r] = 0.0f;

    // prologue: fill STAGES-1 stages
    load_stage(sb, Ab, Wb, 0, tid);
    CP_COMMIT();
    load_stage(sb + STAGE_WORDS * 4, Ab, Wb, 1, tid);
    CP_COMMIT();

    for (int k = 0; k < K_ITERS; k++) {
        CP_WAIT(1);
        __syncthreads();

        // prefetch kiter k+2 into stage (k+2)%3 (computed at iter k-1; all
        // threads passed this barrier => done reading it)
        if (k + STAGES - 1 < K_ITERS) {
            load_stage(sb + (uint32_t)(((k + 2) % 3) * (STAGE_WORDS * 4)), Ab, Wb, k + 2, tid);
        }
        CP_COMMIT();  // always commit (possibly empty) to keep wait_group accounting exact

        const float* sA = smem + (k % 3) * STAGE_WORDS;
        const float* sB = sA + A_STAGE_WORDS;

#pragma unroll
        for (int ks = 0; ks < 4; ks++) {
            uint32_t af[MF][4];
#pragma unroll
            for (int mf = 0; mf < MF; mf++) {
                int r0 = wm * WM + mf * 16 + g;
                int c0 = ks * 8 + tg;
                af[mf][0] = f2tf32(sA[r0 * LDA + c0]);
                af[mf][1] = f2tf32(sA[(r0 + 8) * LDA + c0]);
                af[mf][2] = f2tf32(sA[r0 * LDA + c0 + 4]);
                af[mf][3] = f2tf32(sA[(r0 + 8) * LDA + c0 + 4]);
            }
#pragma unroll
            for (int nf = 0; nf < NF; nf++) {
                int nrow = wn * WN + nf * 8 + g;
                int kc = ks * 8 + tg;
                uint32_t b0 = f2tf32(sB[nrow * LDB + kc]);
                uint32_t b1 = f2tf32(sB[nrow * LDB + kc + 4]);
#pragma unroll
                for (int mf = 0; mf < MF; mf++) {
                    mma_tf32(acc[mf][nf], af[mf], b0, b1);
                }
            }
        }
    }

    // epilogue: direct STG.64 per c-pair
    int mrow_base = m0 + wm * WM;
    int ncol_base = n0 + wn * WN;
#pragma unroll
    for (int mf = 0; mf < MF; mf++) {
        float* prow = out + (size_t)(mrow_base + mf * 16 + g) * N_TOTAL + ncol_base + 2 * tg;
#pragma unroll
        for (int nf = 0; nf < NF; nf++) {
            float2 v0 = make_float2(acc[mf][nf][0], acc[mf][nf][1]);
            float2 v1 = make_float2(acc[mf][nf][2], acc[mf][nf][3]);
            *reinterpret_cast<float2*>(prow + nf * 8) = v0;
            *reinterpret_cast<float2*>(prow + nf * 8 + 8 * N_TOTAL) = v1;
        }
    }
}

// ---------------------------------------------------------------- launch
extern "C" void kernel_launch(void* const* d_in, const int* in_sizes, int n_in,
                              void* d_out, int out_size) {
    const float* A = (const float*)d_in[0];   // [16384, 2048]
    const float* W = (const float*)d_in[1];   // [8, 8192, 2048]
    float* out = (float*)d_out;               // [16384, 8192]
    (void)in_sizes; (void)n_in; (void)out_size;

    cudaFuncSetAttribute(moe_tf32_mma, cudaFuncAttributeMaxDynamicSharedMemorySize,
                         (int)SMEM_BYTES);
    moe_tf32_mma<<<GRID_TILES, THREADS, SMEM_BYTES>>>(A, W, out);
}

// round 3
// speedup vs baseline: 1.0344x; 1.0344x over previous
#include <cuda_runtime.h>
#include <cstdint>

// ============================================================================
// Grouped GEMM (MoE ParallelExperts): out[T,N] = concat_e( A_e @ W_e^T )
//   A: [16384, 2048] fp32, W: [8, 8192, 2048] fp32, 2048 tokens/expert (static)
//
// Two-phase:
//   1) preconvert A and W to tf32 bit patterns (cvt.rna) into __device__ scratch
//   2) tf32 mma.sync (m16n8k8) GEMM, cp.async 3-stage pipeline, inner loop is
//      pure LDS + MMA (no per-fragment cvt -> more issue slots for tensor pipe)
//
// NOTE: harness compiles PTX at target sm_103 (no 'a') -> tcgen05 unavailable;
// mma.sync is the fastest arch-agnostic tensor path.
// ============================================================================

#define M_TOTAL 16384
#define K_TOTAL 2048
#define N_TOTAL 8192
#define NUM_EXPERTS 8
#define M_PER_EXPERT 2048

#define BM 128
#define BN 256
#define BK 32
#define STAGES 3
#define K_ITERS (K_TOTAL / BK)            // 64
#define THREADS 256

#define LDA 36                             // padded word stride: bank-conflict-free frags
#define LDB 36
#define A_STAGE_WORDS (BM * LDA)           // 4608
#define B_STAGE_WORDS (BN * LDB)           // 9216
#define STAGE_WORDS (A_STAGE_WORDS + B_STAGE_WORDS)
#define SMEM_BYTES (STAGES * STAGE_WORDS * 4)   // 165888

#define M_TILES_PER_E (M_PER_EXPERT / BM)  // 16
#define N_TILES (N_TOTAL / BN)             // 32
#define TILES_PER_E (M_TILES_PER_E * N_TILES)
#define GRID_TILES (NUM_EXPERTS * TILES_PER_E)  // 4096

// warp grid 2(m) x 4(n); warp tile 64x64 (optimal LDS/MMA ratio at 8 warps)
#define WM 64
#define WN 64
#define MF 4   // m-frags of 16 rows
#define NF 8   // n-frags of 8 cols

// ---------------------------------------------------------------- scratch
// tf32-converted operands (bit patterns in uint32). __device__ globals are the
// sanctioned scratch mechanism (no allocations allowed in kernel_launch).
__device__ uint32_t g_Ac[M_TOTAL * K_TOTAL];                 // 128 MB
__device__ uint32_t g_Wc[NUM_EXPERTS * N_TOTAL * K_TOTAL];   // 512 MB

// ---------------------------------------------------------------- helpers
__device__ __forceinline__ uint32_t smem_u32(const void* p) {
    uint32_t a;
    asm("{ .reg .u64 t; cvta.to.shared.u64 t, %1; cvt.u32.u64 %0, t; }" : "=r"(a) : "l"(p));
    return a;
}

__device__ __forceinline__ void cp_async16(uint32_t dst, const void* src) {
    asm volatile("cp.async.cg.shared.global [%0], [%1], 16;" :: "r"(dst), "l"(src));
}
#define CP_COMMIT() asm volatile("cp.async.commit_group;" ::: "memory")
#define CP_WAIT(n)  asm volatile("cp.async.wait_group %0;" :: "n"(n) : "memory")

__device__ __forceinline__ uint32_t f2tf32(float f) {
    uint32_t u;
    asm("cvt.rna.tf32.f32 %0, %1;" : "=r"(u) : "f"(f));
    return u;
}

__device__ __forceinline__ void mma_tf32(float* c, const uint32_t* a, uint32_t b0, uint32_t b1) {
    asm volatile(
        "mma.sync.aligned.m16n8k8.row.col.f32.tf32.tf32.f32 "
        "{%0,%1,%2,%3}, {%4,%5,%6,%7}, {%8,%9}, {%0,%1,%2,%3};"
        : "+f"(c[0]), "+f"(c[1]), "+f"(c[2]), "+f"(c[3])
        : "r"(a[0]), "r"(a[1]), "r"(a[2]), "r"(a[3]), "r"(b0), "r"(b1));
}

// ---------------------------------------------------------------- preconvert
__global__ void __launch_bounds__(256)
convert_tf32(const float4* __restrict__ src, uint4* __restrict__ dst, int n4) {
    int i = blockIdx.x * blockDim.x + threadIdx.x;
    int stride = gridDim.x * blockDim.x;
    for (; i < n4; i += stride) {
        float4 v = src[i];
        uint4 o;
        o.x = f2tf32(v.x);
        o.y = f2tf32(v.y);
        o.z = f2tf32(v.z);
        o.w = f2tf32(v.w);
        dst[i] = o;
    }
}

// ---------------------------------------------------------------- stage load
__device__ __forceinline__ void load_stage(uint32_t stage_addr, const uint32_t* Abase,
                                           const uint32_t* Wbase, int kiter, int tid) {
    const char* asrc = (const char*)Abase + (size_t)kiter * (BK * 4);
#pragma unroll
    for (int i = 0; i < 4; i++) {               // A: 128 rows x 8 chunks = 1024
        int q = tid + i * THREADS;
        int row = q >> 3;
        int c = (q & 7) * 16;
        cp_async16(stage_addr + (uint32_t)(row * (LDA * 4) + c),
                   asrc + (size_t)row * (K_TOTAL * 4) + c);
    }
    const char* bsrc = (const char*)Wbase + (size_t)kiter * (BK * 4);
    uint32_t bdst = stage_addr + A_STAGE_WORDS * 4;
#pragma unroll
    for (int i = 0; i < 8; i++) {               // B: 256 rows x 8 chunks = 2048
        int q = tid + i * THREADS;
        int row = q >> 3;
        int c = (q & 7) * 16;
        cp_async16(bdst + (uint32_t)(row * (LDB * 4) + c),
                   bsrc + (size_t)row * (K_TOTAL * 4) + c);
    }
}

// ---------------------------------------------------------------- kernel
__global__ void __launch_bounds__(THREADS, 1)
moe_tf32_mma(float* __restrict__ out) {
    extern __shared__ uint32_t smem[];
    uint32_t sb = smem_u32(smem);
    int tid = threadIdx.x;
    int lane = tid & 31;
    int warp = tid >> 5;
    int wm = warp >> 2;        // 0..1
    int wn = warp & 3;         // 0..3
    int g = lane >> 2;         // group id 0..7
    int tg = lane & 3;         // thread-in-group 0..3

    // tile mapping: expert-major, m fast within expert
    int b = blockIdx.x;
    int e = b / TILES_PER_E;
    int loc = b % TILES_PER_E;
    int m_idx = loc & (M_TILES_PER_E - 1);
    int n_idx = loc >> 4;
    int m0 = e * M_PER_EXPERT + m_idx * BM;
    int n0 = n_idx * BN;

    const uint32_t* Ab = g_Ac + (size_t)m0 * K_TOTAL;
    const uint32_t* Wb = g_Wc + ((size_t)e * N_TOTAL + (size_t)n0) * K_TOTAL;

    float acc[MF][NF][4];
#pragma unroll
    for (int mf = 0; mf < MF; mf++)
#pragma unroll
        for (int nf = 0; nf < NF; nf++)
#pragma unroll
            for (int r = 0; r < 4; r++) acc[mf][nf][r] = 0.0f;

    // prologue: fill STAGES-1 stages
    load_stage(sb, Ab, Wb, 0, tid);
    CP_COMMIT();
    load_stage(sb + STAGE_WORDS * 4, Ab, Wb, 1, tid);
    CP_COMMIT();

    for (int k = 0; k < K_ITERS; k++) {
        CP_WAIT(1);
        __syncthreads();

        // prefetch kiter k+2 into stage (k+2)%3 (all threads passed the
        // barrier above => everyone is done reading that stage)
        if (k + STAGES - 1 < K_ITERS) {
            load_stage(sb + (uint32_t)(((k + 2) % 3) * (STAGE_WORDS * 4)), Ab, Wb, k + 2, tid);
        }
        CP_COMMIT();  // always commit (possibly empty) to keep wait_group accounting exact

        const uint32_t* sA = smem + (k % 3) * STAGE_WORDS;
        const uint32_t* sB = sA + A_STAGE_WORDS;

#pragma unroll
        for (int ks = 0; ks < 4; ks++) {
            uint32_t af[MF][4];
#pragma unroll
            for (int mf = 0; mf < MF; mf++) {
                int r0 = wm * WM + mf * 16 + g;
                int c0 = ks * 8 + tg;
                af[mf][0] = sA[r0 * LDA + c0];
                af[mf][1] = sA[(r0 + 8) * LDA + c0];
                af[mf][2] = sA[r0 * LDA + c0 + 4];
                af[mf][3] = sA[(r0 + 8) * LDA + c0 + 4];
            }
#pragma unroll
            for (int nf = 0; nf < NF; nf++) {
                int nrow = wn * WN + nf * 8 + g;
                int kc = ks * 8 + tg;
                uint32_t b0 = sB[nrow * LDB + kc];
                uint32_t b1 = sB[nrow * LDB + kc + 4];
#pragma unroll
                for (int mf = 0; mf < MF; mf++) {
                    mma_tf32(acc[mf][nf], af[mf], b0, b1);
                }
            }
        }
    }

    // epilogue: direct STG.64 per c-pair
    int mrow_base = m0 + wm * WM;
    int ncol_base = n0 + wn * WN;
#pragma unroll
    for (int mf = 0; mf < MF; mf++) {
        float* prow = out + (size_t)(mrow_base + mf * 16 + g) * N_TOTAL + ncol_base + 2 * tg;
#pragma unroll
        for (int nf = 0; nf < NF; nf++) {
            float2 v0 = make_float2(acc[mf][nf][0], acc[mf][nf][1]);
            float2 v1 = make_float2(acc[mf][nf][2], acc[mf][nf][3]);
            *reinterpret_cast<float2*>(prow + nf * 8) = v0;
            *reinterpret_cast<float2*>(prow + nf * 8 + 8 * N_TOTAL) = v1;
        }
    }
}

// ---------------------------------------------------------------- launch
extern "C" void kernel_launch(void* const* d_in, const int* in_sizes, int n_in,
                              void* d_out, int out_size) {
    const float* A = (const float*)d_in[0];   // [16384, 2048]
    const float* W = (const float*)d_in[1];   // [8, 8192, 2048]
    float* out = (float*)d_out;               // [16384, 8192]
    (void)in_sizes; (void)n_in; (void)out_size;

    // resolve scratch symbol addresses (no allocation; just address lookup)
    void* ac_ptr = nullptr;
    void* wc_ptr = nullptr;
    cudaGetSymbolAddress(&ac_ptr, g_Ac);
    cudaGetSymbolAddress(&wc_ptr, g_Wc);

    // phase 1: preconvert A and W to tf32 bit patterns (rna rounding)
    {
        int nA4 = (M_TOTAL * K_TOTAL) / 4;                 // 8.4M float4
        int nW4 = (NUM_EXPERTS * N_TOTAL * K_TOTAL) / 4;   // 33.6M float4
        convert_tf32<<<4096, 256>>>((const float4*)A, (uint4*)ac_ptr, nA4);
        convert_tf32<<<8192, 256>>>((const float4*)W, (uint4*)wc_ptr, nW4);
    }

    // phase 2: GEMM (same stream -> ordered after conversion, graph-capture safe)
    cudaFuncSetAttribute(moe_tf32_mma, cudaFuncAttributeMaxDynamicSharedMemorySize,
                         (int)SMEM_BYTES);
    moe_tf32_mma<<<GRID_TILES, THREADS, SMEM_BYTES>>>(out);
}

// round 4
// speedup vs baseline: 1.2623x; 1.2204x over previous
#include <cuda_runtime.h>
#include <cstdint>

// ============================================================================
// Grouped GEMM (MoE ParallelExperts): out[T,N] = concat_e( A_e @ W_e^T )
//   A: [16384, 2048] fp32, W: [8, 8192, 2048] fp32, 2048 tokens/expert (static)
//
// Two-phase:
//   1) permute+convert A and W into MMA-fragment-ordered tf32 scratch:
//      512B blocks where thread `lane` reads its 4 mma.sync regs as one LDS.128
//   2) tf32 mma.sync (m16n8k8) GEMM, cp.async 3-stage pipeline; inner loop is
//      32 LDS.128 + 128 MMA per warp per K-iter (was 128 LDS.32 + 128 CVT +
//      128 MMA) -> issue slots and load->use distance for the tensor pipe
//
// NOTE: harness compiles PTX at target sm_103 (no 'a') -> tcgen05 unavailable;
// mma.sync is the fastest arch-agnostic tensor path.
// ============================================================================

#define M_TOTAL 16384
#define K_TOTAL 2048
#define N_TOTAL 8192
#define NUM_EXPERTS 8
#define M_PER_EXPERT 2048

#define BM 128
#define BN 256
#define BK 32
#define STAGES 3
#define K_ITERS (K_TOTAL / BK)             // 64
#define THREADS 256

#define M_TILES (M_TOTAL / BM)             // 128 (global; expert-aligned)
#define M_TILES_PER_E (M_PER_EXPERT / BM)  // 16
#define N_TILES (N_TOTAL / BN)             // 32
#define TILES_PER_E (M_TILES_PER_E * N_TILES)
#define GRID_TILES (NUM_EXPERTS * TILES_PER_E)  // 4096

// fragment-ordered stage: A slab 16KB (8 m16-blocks x 4 ks x 512B),
//                         B slab 32KB (32 n8-blocks x 2 ks2 x 512B)
#define A_STAGE_WORDS (BM * BK)            // 4096
#define B_STAGE_WORDS (BN * BK)            // 8192
#define STAGE_WORDS (A_STAGE_WORDS + B_STAGE_WORDS)   // 12288
#define SMEM_BYTES (STAGES * STAGE_WORDS * 4)         // 147456

// warp grid 2(m) x 4(n); warp tile 64x64
#define WM 64
#define WN 64
#define MF 4   // m-frags of 16 rows
#define NF 8   // n-frags of 8 cols

// ---------------------------------------------------------------- scratch
// fragment-permuted tf32 operands. __device__ globals = sanctioned scratch.
__device__ uint32_t g_Ac[M_TOTAL * K_TOTAL];                 // 128 MB
__device__ uint32_t g_Wc[NUM_EXPERTS * N_TOTAL * K_TOTAL];   // 512 MB

// ---------------------------------------------------------------- helpers
__device__ __forceinline__ uint32_t smem_u32(const void* p) {
    uint32_t a;
    asm("{ .reg .u64 t; cvta.to.shared.u64 t, %1; cvt.u32.u64 %0, t; }" : "=r"(a) : "l"(p));
    return a;
}

__device__ __forceinline__ void cp_async16(uint32_t dst, const void* src) {
    asm volatile("cp.async.cg.shared.global [%0], [%1], 16;" :: "r"(dst), "l"(src));
}
#define CP_COMMIT() asm volatile("cp.async.commit_group;" ::: "memory")
#define CP_WAIT(n)  asm volatile("cp.async.wait_group %0;" :: "n"(n) : "memory")

__device__ __forceinline__ uint32_t f2tf32(float f) {
    uint32_t u;
    asm("cvt.rna.tf32.f32 %0, %1;" : "=r"(u) : "f"(f));
    return u;
}

__device__ __forceinline__ void mma_tf32(float* c, const uint32_t* a, uint32_t b0, uint32_t b1) {
    asm volatile(
        "mma.sync.aligned.m16n8k8.row.col.f32.tf32.tf32.f32 "
        "{%0,%1,%2,%3}, {%4,%5,%6,%7}, {%8,%9}, {%0,%1,%2,%3};"
        : "+f"(c[0]), "+f"(c[1]), "+f"(c[2]), "+f"(c[3])
        : "r"(a[0]), "r"(a[1]), "r"(a[2]), "r"(a[3]), "r"(b0), "r"(b1));
}

// ---------------------------------------------------------------- permute A
// A_perm block id = ((mt*64 + kc)*8 + mblk)*4 + ks ; block = 512B, one warp.
// lane (g=l>>2, tg=l&3) regs: A[r0+g][c0+tg], A[r0+g+8][c0+tg],
//                             A[r0+g][c0+tg+4], A[r0+g+8][c0+tg+4]
__global__ void __launch_bounds__(256)
permute_A(const float* __restrict__ A) {
    int wid = (blockIdx.x * blockDim.x + threadIdx.x) >> 5;   // block id
    int lane = threadIdx.x & 31;
    int ks = wid & 3;
    int mblk = (wid >> 2) & 7;
    int kc = (wid >> 5) & 63;
    int mt = wid >> 11;                    // 0..127
    int g = lane >> 2, tg = lane & 3;
    int r0 = mt * BM + mblk * 16;
    int c0 = kc * BK + ks * 8;
    const float* p = A + (size_t)(r0 + g) * K_TOTAL + c0 + tg;
    uint4 o;
    o.x = f2tf32(p[0]);
    o.y = f2tf32(p[(size_t)8 * K_TOTAL]);
    o.z = f2tf32(p[4]);
    o.w = f2tf32(p[(size_t)8 * K_TOTAL + 4]);
    reinterpret_cast<uint4*>(g_Ac)[(size_t)wid * 32 + lane] = o;
}

// ---------------------------------------------------------------- permute W
// W_perm block id = (((e*32 + nt)*64 + kc)*64 + nblk*2 + ks2) ; 512B, one warp.
// lane regs (n8 x k16 tile): W[nrow][kb+tg], W[nrow][kb+tg+4],
//                            W[nrow][kb+8+tg], W[nrow][kb+8+tg+4]
__global__ void __launch_bounds__(256)
permute_W(const float* __restrict__ W) {
    int wid = (blockIdx.x * blockDim.x + threadIdx.x) >> 5;
    int lane = threadIdx.x & 31;
    int ks2 = wid & 1;
    int nblk = (wid >> 1) & 31;
    int kc = (wid >> 6) & 63;
    int nt = (wid >> 12) & 31;
    int e = wid >> 17;
    int g = lane >> 2, tg = lane & 3;
    int nrow = nt * BN + nblk * 8 + g;
    int kb = kc * BK + ks2 * 16;
    const float* p = W + ((size_t)e * N_TOTAL + nrow) * K_TOTAL + kb + tg;
    uint4 o;
    o.x = f2tf32(p[0]);
    o.y = f2tf32(p[4]);
    o.z = f2tf32(p[8]);
    o.w = f2tf32(p[12]);
    reinterpret_cast<uint4*>(g_Wc)[(size_t)wid * 32 + lane] = o;
}

// ---------------------------------------------------------------- stage load
// stage slabs are fully contiguous in scratch -> plain linear cp.async
__device__ __forceinline__ void load_stage(uint32_t stage_addr, const uint32_t* Aslab,
                                           const uint32_t* Bslab, int tid) {
    const char* asrc = (const char*)Aslab;
#pragma unroll
    for (int i = 0; i < 4; i++) {               // A: 16KB = 1024 chunks
        int q = tid + i * THREADS;
        cp_async16(stage_addr + (uint32_t)q * 16, asrc + (size_t)q * 16);
    }
    const char* bsrc = (const char*)Bslab;
    uint32_t bdst = stage_addr + A_STAGE_WORDS * 4;
#pragma unroll
    for (int i = 0; i < 8; i++) {               // B: 32KB = 2048 chunks
        int q = tid + i * THREADS;
        cp_async16(bdst + (uint32_t)q * 16, bsrc + (size_t)q * 16);
    }
}

// ---------------------------------------------------------------- kernel
__global__ void __launch_bounds__(THREADS, 1)
moe_tf32_mma(float* __restrict__ out) {
    extern __shared__ uint32_t smem[];
    uint32_t sb = smem_u32(smem);
    int tid = threadIdx.x;
    int lane = tid & 31;
    int warp = tid >> 5;
    int wm = warp >> 2;        // 0..1
    int wn = warp & 3;         // 0..3
    int g = lane >> 2;         // group id 0..7
    int tg = lane & 3;         // thread-in-group 0..3

    // tile mapping: expert-major, m fast within expert
    int b = blockIdx.x;
    int e = b / TILES_PER_E;
    int loc = b % TILES_PER_E;
    int m_idx = loc & (M_TILES_PER_E - 1);
    int n_idx = loc >> 4;
    int mt = e * M_TILES_PER_E + m_idx;    // global m-tile
    int m0 = mt * BM;
    int n0 = n_idx * BN;

    // per-(tile, k-chunk) slabs in permuted scratch
    const uint32_t* Abase = g_Ac + (size_t)mt * 64 * A_STAGE_WORDS;
    const uint32_t* Bbase = g_Wc + ((size_t)(e * N_TILES + n_idx)) * 64 * B_STAGE_WORDS;

    float acc[MF][NF][4];
#pragma unroll
    for (int mf = 0; mf < MF; mf++)
#pragma unroll
        for (int nf = 0; nf < NF; nf++)
#pragma unroll
            for (int r = 0; r < 4; r++) acc[mf][nf][r] = 0.0f;

    // prologue: fill STAGES-1 stages
    load_stage(sb, Abase, Bbase, tid);
    CP_COMMIT();
    load_stage(sb + STAGE_WORDS * 4, Abase + A_STAGE_WORDS, Bbase + B_STAGE_WORDS, tid);
    CP_COMMIT();

    for (int k = 0; k < K_ITERS; k++) {
        CP_WAIT(1);
        __syncthreads();

        if (k + STAGES - 1 < K_ITERS) {
            int kn = k + 2;
            load_stage(sb + (uint32_t)((kn % 3) * (STAGE_WORDS * 4)),
                       Abase + (size_t)kn * A_STAGE_WORDS,
                       Bbase + (size_t)kn * B_STAGE_WORDS, tid);
        }
        CP_COMMIT();  // always commit (possibly empty) to keep accounting exact

        const uint4* sA4 = reinterpret_cast<const uint4*>(smem + (k % 3) * STAGE_WORDS);
        const uint4* sB4 = sA4 + (A_STAGE_WORDS / 4);

#pragma unroll
        for (int ks2 = 0; ks2 < 2; ks2++) {
            uint4 bf[NF];
#pragma unroll
            for (int nf = 0; nf < NF; nf++)
                bf[nf] = sB4[((wn * 8 + nf) * 2 + ks2) * 32 + lane];
#pragma unroll
            for (int ksi = 0; ksi < 2; ksi++) {
                int ks = ks2 * 2 + ksi;
                uint4 af[MF];
#pragma unroll
                for (int mf = 0; mf < MF; mf++)
                    af[mf] = sA4[((wm * 4 + mf) * 4 + ks) * 32 + lane];
#pragma unroll
                for (int nf = 0; nf < NF; nf++) {
                    uint32_t b0 = ksi ? bf[nf].z : bf[nf].x;
                    uint32_t b1 = ksi ? bf[nf].w : bf[nf].y;
#pragma unroll
                    for (int mf = 0; mf < MF; mf++)
                        mma_tf32(acc[mf][nf], reinterpret_cast<const uint32_t*>(&af[mf]), b0, b1);
                }
            }
        }
    }

    // epilogue: direct STG.64 per c-pair
    int mrow_base = m0 + wm * WM;
    int ncol_base = n0 + wn * WN;
#pragma unroll
    for (int mf = 0; mf < MF; mf++) {
        float* prow = out + (size_t)(mrow_base + mf * 16 + g) * N_TOTAL + ncol_base + 2 * tg;
#pragma unroll
        for (int nf = 0; nf < NF; nf++) {
            float2 v0 = make_float2(acc[mf][nf][0], acc[mf][nf][1]);
            float2 v1 = make_float2(acc[mf][nf][2], acc[mf][nf][3]);
            *reinterpret_cast<float2*>(prow + nf * 8) = v0;
            *reinterpret_cast<float2*>(prow + nf * 8 + 8 * N_TOTAL) = v1;
        }
    }
}

// ---------------------------------------------------------------- launch
extern "C" void kernel_launch(void* const* d_in, const int* in_sizes, int n_in,
                              void* d_out, int out_size) {
    const float* A = (const float*)d_in[0];   // [16384, 2048]
    const float* W = (const float*)d_in[1];   // [8, 8192, 2048]
    float* out = (float*)d_out;               // [16384, 8192]
    (void)in_sizes; (void)n_in; (void)out_size;

    // phase 1: permute+convert to fragment-ordered tf32 scratch
    {
        int a_blocks = M_TILES * 64 * 8 * 4;              // 262144 warps
        int w_blocks = NUM_EXPERTS * N_TILES * 64 * 64;   // 1048576 warps
        permute_A<<<a_blocks / 8, 256>>>(A);              // 8 warps per CTA
        permute_W<<<w_blocks / 8, 256>>>(W);
    }

    // phase 2: GEMM (same stream -> ordered after conversion)
    cudaFuncSetAttribute(moe_tf32_mma, cudaFuncAttributeMaxDynamicSharedMemorySize,
                         (int)SMEM_BYTES);
    moe_tf32_mma<<<GRID_TILES, THREADS, SMEM_BYTES>>>(out);
}